// round 15
// baseline (speedup 1.0000x reference)
#include <cuda_runtime.h>
#include <cstdint>

// Embedding gather — R13 shape + streaming (evict-first) output stores.
// x: [32768] int32; emb: [50257, 512] f32; out: [32768, 512] f32.
// even ids -> id 0 (reference: jnp.where(x % 2 == 0, 0, x)).
//
// Theory: table (103MB) + output (64MB) > L2 (126MB). Regular stores keep
// output lines resident, evicting the table and pushing gather reads to
// DRAM (latency wall). st.global.cs marks output evict-first, so the table
// stays L2-resident: gathers become ~260cyc L2 hits; writes stream to the
// 70%-idle DRAM with no latency exposure.

static constexpr int VEC_PER_ROW    = 128;  // float4 per row
static constexpr int ROWS_PER_BLOCK = 32;
static constexpr int THREADS        = 512;

__device__ __forceinline__ void stg_cs(float4* p, float4 v) {
    asm volatile("st.global.cs.v4.f32 [%0], {%1,%2,%3,%4};"
                 :: "l"(p), "f"(v.x), "f"(v.y), "f"(v.z), "f"(v.w)
                 : "memory");
}

__global__ __launch_bounds__(THREADS)
void embed_gather_kernel(const int* __restrict__ x,
                         const float4* __restrict__ emb,
                         float4* __restrict__ out) {
    const int base = blockIdx.x * ROWS_PER_BLOCK;
    const int tid  = threadIdx.x;

    // chunk c covers rows {4c .. 4c+3}: thread group tid>>7 (0..3) owns row
    // 4c + (tid>>7); col = tid & 127 (fully coalesced 128B per warp).
    const int rhi = tid >> 7;         // 0..3, warp-uniform
    const int col = tid & 127;

    const int* xb = x + base + rhi;

    // Warp-uniform broadcast id loads.
    int t0 = __ldg(xb +  0);
    int t1 = __ldg(xb +  4);
    int t2 = __ldg(xb +  8);
    int t3 = __ldg(xb + 12);
    int t4 = __ldg(xb + 16);
    int t5 = __ldg(xb + 20);
    int t6 = __ldg(xb + 24);
    int t7 = __ldg(xb + 28);

    t0 = (t0 & 1) ? t0 : 0;   // even ids -> row 0
    t1 = (t1 & 1) ? t1 : 0;
    t2 = (t2 & 1) ? t2 : 0;
    t3 = (t3 & 1) ? t3 : 0;
    t4 = (t4 & 1) ? t4 : 0;
    t5 = (t5 & 1) ? t5 : 0;
    t6 = (t6 & 1) ? t6 : 0;
    t7 = (t7 & 1) ? t7 : 0;

    // 8 independent gathers (MLP-8 read path).
    float4 v0 = __ldg(emb + (size_t)t0 * VEC_PER_ROW + col);
    float4 v1 = __ldg(emb + (size_t)t1 * VEC_PER_ROW + col);
    float4 v2 = __ldg(emb + (size_t)t2 * VEC_PER_ROW + col);
    float4 v3 = __ldg(emb + (size_t)t3 * VEC_PER_ROW + col);
    float4 v4 = __ldg(emb + (size_t)t4 * VEC_PER_ROW + col);
    float4 v5 = __ldg(emb + (size_t)t5 * VEC_PER_ROW + col);
    float4 v6 = __ldg(emb + (size_t)t6 * VEC_PER_ROW + col);
    float4 v7 = __ldg(emb + (size_t)t7 * VEC_PER_ROW + col);

    // Streaming stores: chunk c writes flat float4 index c*512 + tid.
    float4* dst = out + (size_t)base * VEC_PER_ROW + tid;
    stg_cs(dst + 0 * THREADS, v0);
    stg_cs(dst + 1 * THREADS, v1);
    stg_cs(dst + 2 * THREADS, v2);
    stg_cs(dst + 3 * THREADS, v3);
    stg_cs(dst + 4 * THREADS, v4);
    stg_cs(dst + 5 * THREADS, v5);
    stg_cs(dst + 6 * THREADS, v6);
    stg_cs(dst + 7 * THREADS, v7);
}

extern "C" void kernel_launch(void* const* d_in, const int* in_sizes, int n_in,
                              void* d_out, int out_size) {
    const int* x      = (const int*)d_in[0];
    const float4* emb = (const float4*)d_in[1];
    float4* out       = (float4*)d_out;

    int n_rows   = in_sizes[0];                 // 32768 (multiple of 32)
    int n_blocks = n_rows / ROWS_PER_BLOCK;     // 1024

    embed_gather_kernel<<<n_blocks, THREADS>>>(x, emb, out);
}

// round 16
// speedup vs baseline: 1.0194x; 1.0194x over previous
#include <cuda_runtime.h>
#include <cstdint>

// Embedding gather — R13 body, persistent at FULL occupancy (sm_103a).
// x: [32768] int32; emb: [50257, 512] f32; out: [32768, 512] f32.
// even ids -> id 0 (reference: jnp.where(x % 2 == 0, 0, x)).
//
// Grid = 592 CTAs x 512 thr = exactly 4 CTAs/SM * 148 SMs (2048 thr/SM,
// 100% residency). Each CTA grid-strides over 32-row tiles (~2 tiles);
// iterations are fully self-contained (no loop-carried registers), so
// this removes the 1.73-wave quantization tail + wave-2 cold ramp that
// capped the one-shot version at occ ~71%.

static constexpr int VEC_PER_ROW    = 128;  // float4 per row
static constexpr int ROWS_PER_BLOCK = 32;
static constexpr int THREADS        = 512;
static constexpr int GRID           = 592;  // 4 CTAs/SM * 148 SMs

__device__ __forceinline__ void stg_cs(float4* p, float4 v) {
    asm volatile("st.global.cs.v4.f32 [%0], {%1,%2,%3,%4};"
                 :: "l"(p), "f"(v.x), "f"(v.y), "f"(v.z), "f"(v.w)
                 : "memory");
}

__global__ __launch_bounds__(THREADS)
void embed_gather_kernel(const int* __restrict__ x,
                         const float4* __restrict__ emb,
                         float4* __restrict__ out,
                         int n_tiles) {
    const int tid = threadIdx.x;
    const int rhi = tid >> 7;         // 0..3, warp-uniform row subgroup
    const int col = tid & 127;        // float4 column (128B/warp coalesced)

    for (int t = blockIdx.x; t < n_tiles; t += GRID) {
        const int base = t * ROWS_PER_BLOCK;
        const int* xb = x + base + rhi;

        // Warp-uniform broadcast id loads (chunk c -> row 4c + rhi).
        int t0 = __ldg(xb +  0);
        int t1 = __ldg(xb +  4);
        int t2 = __ldg(xb +  8);
        int t3 = __ldg(xb + 12);
        int t4 = __ldg(xb + 16);
        int t5 = __ldg(xb + 20);
        int t6 = __ldg(xb + 24);
        int t7 = __ldg(xb + 28);

        t0 = (t0 & 1) ? t0 : 0;   // even ids -> row 0
        t1 = (t1 & 1) ? t1 : 0;
        t2 = (t2 & 1) ? t2 : 0;
        t3 = (t3 & 1) ? t3 : 0;
        t4 = (t4 & 1) ? t4 : 0;
        t5 = (t5 & 1) ? t5 : 0;
        t6 = (t6 & 1) ? t6 : 0;
        t7 = (t7 & 1) ? t7 : 0;

        // 8 independent gathers (MLP-8 read path).
        float4 v0 = __ldg(emb + (size_t)t0 * VEC_PER_ROW + col);
        float4 v1 = __ldg(emb + (size_t)t1 * VEC_PER_ROW + col);
        float4 v2 = __ldg(emb + (size_t)t2 * VEC_PER_ROW + col);
        float4 v3 = __ldg(emb + (size_t)t3 * VEC_PER_ROW + col);
        float4 v4 = __ldg(emb + (size_t)t4 * VEC_PER_ROW + col);
        float4 v5 = __ldg(emb + (size_t)t5 * VEC_PER_ROW + col);
        float4 v6 = __ldg(emb + (size_t)t6 * VEC_PER_ROW + col);
        float4 v7 = __ldg(emb + (size_t)t7 * VEC_PER_ROW + col);

        // Streaming stores: chunk c writes flat float4 index c*512 + tid.
        float4* dst = out + (size_t)base * VEC_PER_ROW + tid;
        stg_cs(dst + 0 * THREADS, v0);
        stg_cs(dst + 1 * THREADS, v1);
        stg_cs(dst + 2 * THREADS, v2);
        stg_cs(dst + 3 * THREADS, v3);
        stg_cs(dst + 4 * THREADS, v4);
        stg_cs(dst + 5 * THREADS, v5);
        stg_cs(dst + 6 * THREADS, v6);
        stg_cs(dst + 7 * THREADS, v7);
    }
}

extern "C" void kernel_launch(void* const* d_in, const int* in_sizes, int n_in,
                              void* d_out, int out_size) {
    const int* x      = (const int*)d_in[0];
    const float4* emb = (const float4*)d_in[1];
    float4* out       = (float4*)d_out;

    int n_rows  = in_sizes[0];               // 32768 (multiple of 32)
    int n_tiles = n_rows / ROWS_PER_BLOCK;   // 1024

    embed_gather_kernel<<<GRID, THREADS>>>(x, emb, out, n_tiles);
}